// round 5
// baseline (speedup 1.0000x reference)
#include <cuda_runtime.h>
#include <cuda_bf16.h>

#define N_NODES 100000
#define IN_F 64
#define OUT_F 64
#define E_MAX 1600000
#define SCAN_BS 1024

// CSR + h scratch
__device__ int g_deg[N_NODES];
__device__ int g_off[N_NODES];
__device__ int g_cursor[N_NODES];
__device__ int g_eidx[E_MAX];
__device__ int g_blocksums[128];
__device__ int g_scan_done;
__device__ float4 g_h4[(size_t)N_NODES * 16];   // h = segment_sum, 25.6MB

// ---------------------------------------------------------------------------
// Packed f32x2 FMA (Blackwell FFMA2 — only reachable via PTX)
// ---------------------------------------------------------------------------
__device__ __forceinline__ unsigned long long fma_f32x2(unsigned long long a,
                                                        unsigned long long b,
                                                        unsigned long long c) {
    unsigned long long d;
    asm("fma.rn.f32x2 %0, %1, %2, %3;" : "=l"(d) : "l"(a), "l"(b), "l"(c));
    return d;
}
__device__ __forceinline__ unsigned long long pack_f32x2(float lo, float hi) {
    unsigned long long r;
    asm("mov.b64 %0, {%1, %2};" : "=l"(r) : "f"(lo), "f"(hi));
    return r;
}
__device__ __forceinline__ float sum_f32x2(unsigned long long v) {
    float lo, hi;
    asm("mov.b64 {%0, %1}, %2;" : "=f"(lo), "=f"(hi) : "l"(v));
    return lo + hi;
}

// ---------------------------------------------------------------------------
// CSR build
// ---------------------------------------------------------------------------
__global__ void zero_deg_kernel(int n) {
    int i = blockIdx.x * blockDim.x + threadIdx.x;
    if (i < n) g_deg[i] = 0;
    if (i == 0) g_scan_done = 0;
}

__global__ void count_deg_kernel(const int* __restrict__ dst, int E) {
    int e = blockIdx.x * blockDim.x + threadIdx.x;
    if (e < E) atomicAdd(&g_deg[dst[e]], 1);
}

// Block-local scan; the LAST block to finish also scans the block sums
// (folds old phase2 into phase1 — one fewer launch).
__global__ void __launch_bounds__(SCAN_BS) scan_phase1(int n, int nb) {
    __shared__ int buf0[SCAN_BS];
    __shared__ int buf1[SCAN_BS];
    int t = threadIdx.x;
    int i = blockIdx.x * SCAN_BS + t;
    int v = (i < n) ? g_deg[i] : 0;
    buf0[t] = v;
    __syncthreads();
    int* in = buf0;
    int* out = buf1;
    #pragma unroll
    for (int off = 1; off < SCAN_BS; off <<= 1) {
        int s = in[t];
        if (t >= off) s += in[t - off];
        out[t] = s;
        __syncthreads();
        int* tmp = in; in = out; out = tmp;
    }
    if (t == SCAN_BS - 1) g_blocksums[blockIdx.x] = in[t];
    if (i < n) g_off[i] = in[t] - v;   // exclusive within block

    // last-block-finishing scans the 98 block sums
    __threadfence();
    __shared__ int s_last;
    if (t == 0) s_last = (atomicAdd(&g_scan_done, 1) == nb - 1) ? 1 : 0;
    __syncthreads();
    if (s_last) {
        __shared__ int bs0[128];
        __shared__ int bs1[128];
        int bv = 0;
        if (t < 128) {
            bv = (t < nb) ? g_blocksums[t] : 0;
            bs0[t] = bv;
        }
        __syncthreads();
        int* bin = bs0;
        int* bout = bs1;
        #pragma unroll
        for (int off = 1; off < 128; off <<= 1) {
            if (t < 128) {
                int s = bin[t];
                if (t >= off) s += bin[t - off];
                bout[t] = s;
            }
            __syncthreads();
            int* tmp = bin; bin = bout; bout = tmp;
        }
        if (t < nb) g_blocksums[t] = bin[t] - bv;  // exclusive
    }
}

// Add block base; init cursor.
__global__ void scan_phase3(int n) {
    int i = blockIdx.x * SCAN_BS + threadIdx.x;
    if (i < n) {
        int s = g_off[i] + g_blocksums[blockIdx.x];
        g_off[i] = s;
        g_cursor[i] = s;
    }
}

__global__ void fill_buckets_kernel(const int* __restrict__ src,
                                    const int* __restrict__ dst, int E) {
    int e = blockIdx.x * blockDim.x + threadIdx.x;
    if (e < E) {
        int pos = atomicAdd(&g_cursor[dst[e]], 1);
        g_eidx[pos] = src[e];
    }
}

// ---------------------------------------------------------------------------
// Gather-aggregate: h[n] = sum_{e: dst[e]=n} x[src[e]].
// 16 threads per node, one float4 lane each. Inner loop unrolled x4 with
// independent loads -> MLP=4+. Small blocks / low regs -> high occupancy.
// ---------------------------------------------------------------------------
__global__ void __launch_bounds__(256)
gather_h_kernel(const float4* __restrict__ x4, int N) {
    int idx = blockIdx.x * blockDim.x + threadIdx.x;
    int node = idx >> 4;
    if (node >= N) return;
    int l = idx & 15;

    int beg = g_off[node];
    int cnt = g_deg[node];

    float4 a0 = make_float4(0.f, 0.f, 0.f, 0.f);
    float4 a1 = a0, a2 = a0, a3 = a0;

    int j = 0;
    for (; j + 4 <= cnt; j += 4) {
        int s0 = __ldg(g_eidx + beg + j + 0);
        int s1 = __ldg(g_eidx + beg + j + 1);
        int s2 = __ldg(g_eidx + beg + j + 2);
        int s3 = __ldg(g_eidx + beg + j + 3);
        float4 v0 = __ldg(x4 + (size_t)s0 * 16 + l);
        float4 v1 = __ldg(x4 + (size_t)s1 * 16 + l);
        float4 v2 = __ldg(x4 + (size_t)s2 * 16 + l);
        float4 v3 = __ldg(x4 + (size_t)s3 * 16 + l);
        a0.x += v0.x; a0.y += v0.y; a0.z += v0.z; a0.w += v0.w;
        a1.x += v1.x; a1.y += v1.y; a1.z += v1.z; a1.w += v1.w;
        a2.x += v2.x; a2.y += v2.y; a2.z += v2.z; a2.w += v2.w;
        a3.x += v3.x; a3.y += v3.y; a3.z += v3.z; a3.w += v3.w;
    }
    for (; j < cnt; j++) {
        int s = __ldg(g_eidx + beg + j);
        float4 v = __ldg(x4 + (size_t)s * 16 + l);
        a0.x += v.x; a0.y += v.y; a0.z += v.z; a0.w += v.w;
    }

    float4 r;
    r.x = (a0.x + a1.x) + (a2.x + a3.x);
    r.y = (a0.y + a1.y) + (a2.y + a3.y);
    r.z = (a0.z + a1.z) + (a2.z + a3.z);
    r.w = (a0.w + a1.w) + (a2.w + a3.w);
    g_h4[(size_t)node * 16 + l] = r;
}

// ---------------------------------------------------------------------------
// Output GEMM with packed f32x2 FMAs, 8 nodes per thread (halves per-node
// weight-smem traffic):
//   out[n][o] = sum_f h[n][f]*W_lin[o][f] + x[n][f]*W_self[o][f] + b[o]
// Block (64,8)=512 threads -> 64 nodes per block.
// ---------------------------------------------------------------------------
__global__ void __launch_bounds__(512)
out_gemm_kernel(const float* __restrict__ x,
                const float* __restrict__ W_lin,
                const float* __restrict__ b_lin,
                const float* __restrict__ W_self,
                const float* __restrict__ b_self,
                const float* __restrict__ bias,
                float* __restrict__ out,
                int N) {
    __shared__ float sWl[64 * 64];   // layout: [f4][o][4]
    __shared__ float sWs[64 * 64];

    int tid = threadIdx.y * 64 + threadIdx.x;
    #pragma unroll
    for (int i = tid; i < 64 * 64; i += 512) {
        int o = i >> 6;
        int f = i & 63;
        int dsti = (f >> 2) * 256 + o * 4 + (f & 3);
        sWl[dsti] = W_lin[i];
        sWs[dsti] = W_self[i];
    }
    __syncthreads();

    int o = threadIdx.x;
    float b = b_lin[o] + b_self[o] + bias[o];

    int n0 = blockIdx.x * 64 + threadIdx.y * 8;
    if (n0 >= N) return;

    const float* __restrict__ hbase = (const float*)g_h4 + (size_t)n0 * 64;
    const float* __restrict__ xbase = x + (size_t)n0 * 64;

    if (n0 + 7 < N) {
        unsigned long long acc[8];
        unsigned long long binit = pack_f32x2(b, 0.f);
        #pragma unroll
        for (int k = 0; k < 8; k++) acc[k] = binit;

        #pragma unroll
        for (int f4 = 0; f4 < 16; f4++) {
            ulonglong2 wl = *reinterpret_cast<const ulonglong2*>(
                                &sWl[f4 * 256 + o * 4]);
            ulonglong2 ws = *reinterpret_cast<const ulonglong2*>(
                                &sWs[f4 * 256 + o * 4]);
            #pragma unroll
            for (int k = 0; k < 8; k++) {
                ulonglong2 h = *reinterpret_cast<const ulonglong2*>(
                                   hbase + k * 64 + f4 * 4);
                ulonglong2 xv = *reinterpret_cast<const ulonglong2*>(
                                    xbase + k * 64 + f4 * 4);
                acc[k] = fma_f32x2(h.x, wl.x, acc[k]);
                acc[k] = fma_f32x2(h.y, wl.y, acc[k]);
                acc[k] = fma_f32x2(xv.x, ws.x, acc[k]);
                acc[k] = fma_f32x2(xv.y, ws.y, acc[k]);
            }
        }

        float* op = out + (size_t)n0 * 64 + o;
        #pragma unroll
        for (int k = 0; k < 8; k++) op[k * 64] = sum_f32x2(acc[k]);
    } else {
        for (int k = 0; k < 8; k++) {
            int n = n0 + k;
            if (n >= N) break;
            float a = b;
            for (int f = 0; f < 64; f++) {
                a += hbase[k * 64 + f] * sWl[(f >> 2) * 256 + o * 4 + (f & 3)]
                   + xbase[k * 64 + f] * sWs[(f >> 2) * 256 + o * 4 + (f & 3)];
            }
            out[(size_t)n * 64 + o] = a;
        }
    }
}

// ---------------------------------------------------------------------------
// Launch. Input order: x, src, dst, W_lin, b_lin, W_self, b_self, bias
// ---------------------------------------------------------------------------
extern "C" void kernel_launch(void* const* d_in, const int* in_sizes, int n_in,
                              void* d_out, int out_size) {
    const float* x      = (const float*)d_in[0];
    const int*   src    = (const int*)d_in[1];
    const int*   dst    = (const int*)d_in[2];
    const float* W_lin  = (const float*)d_in[3];
    const float* b_lin  = (const float*)d_in[4];
    const float* W_self = (const float*)d_in[5];
    const float* b_self = (const float*)d_in[6];
    const float* bias   = (const float*)d_in[7];
    float* out = (float*)d_out;

    int N = in_sizes[0] / IN_F;   // 100000
    int E = in_sizes[1];          // 1280000
    int nb = (N + SCAN_BS - 1) / SCAN_BS;   // 98

    // CSR build
    zero_deg_kernel<<<(N + 255) / 256, 256>>>(N);
    count_deg_kernel<<<(E + 255) / 256, 256>>>(dst, E);
    scan_phase1<<<nb, SCAN_BS>>>(N, nb);
    scan_phase3<<<nb, SCAN_BS>>>(N);
    fill_buckets_kernel<<<(E + 255) / 256, 256>>>(src, dst, E);

    // Aggregate
    long long gt = (long long)N * 16;
    gather_h_kernel<<<(int)((gt + 255) / 256), 256>>>((const float4*)x, N);

    // Output GEMM
    dim3 blk(64, 8);
    out_gemm_kernel<<<(N + 63) / 64, blk>>>(x, W_lin, b_lin, W_self, b_self,
                                            bias, out, N);
}

// round 6
// speedup vs baseline: 1.4801x; 1.4801x over previous
#include <cuda_runtime.h>
#include <cuda_bf16.h>

#define N_NODES 100000
#define IN_F 64
#define OUT_F 64
#define E_MAX 1600000
#define SCAN_BS 1024

// CSR scratch
__device__ int g_deg[N_NODES];
__device__ int g_off[N_NODES];
__device__ int g_cursor[N_NODES];
__device__ int g_eidx[E_MAX];
__device__ int g_blocksums[128];
__device__ int g_scan_done;

// ---------------------------------------------------------------------------
// Packed f32x2 FMA (Blackwell FFMA2 — only reachable via PTX)
// ---------------------------------------------------------------------------
__device__ __forceinline__ unsigned long long fma_f32x2(unsigned long long a,
                                                        unsigned long long b,
                                                        unsigned long long c) {
    unsigned long long d;
    asm("fma.rn.f32x2 %0, %1, %2, %3;" : "=l"(d) : "l"(a), "l"(b), "l"(c));
    return d;
}
__device__ __forceinline__ unsigned long long pack_f32x2(float lo, float hi) {
    unsigned long long r;
    asm("mov.b64 %0, {%1, %2};" : "=l"(r) : "f"(lo), "f"(hi));
    return r;
}
__device__ __forceinline__ float sum_f32x2(unsigned long long v) {
    float lo, hi;
    asm("mov.b64 {%0, %1}, %2;" : "=f"(lo), "=f"(hi) : "l"(v));
    return lo + hi;
}

// ---------------------------------------------------------------------------
// CSR build
// ---------------------------------------------------------------------------
__global__ void zero_deg_kernel(int n) {
    int i = blockIdx.x * blockDim.x + threadIdx.x;
    if (i < n) g_deg[i] = 0;
    if (i == 0) g_scan_done = 0;
}

__global__ void count_deg_kernel(const int* __restrict__ dst, int E) {
    int e = blockIdx.x * blockDim.x + threadIdx.x;
    if (e < E) {
        int* p = &g_deg[dst[e]];
        asm volatile("red.global.add.s32 [%0], 1;" :: "l"(p) : "memory");
    }
}

// Block-local scan; the LAST block to finish also scans the block sums.
__global__ void __launch_bounds__(SCAN_BS) scan_phase1(int n, int nb) {
    __shared__ int buf0[SCAN_BS];
    __shared__ int buf1[SCAN_BS];
    int t = threadIdx.x;
    int i = blockIdx.x * SCAN_BS + t;
    int v = (i < n) ? g_deg[i] : 0;
    buf0[t] = v;
    __syncthreads();
    int* in = buf0;
    int* out = buf1;
    #pragma unroll
    for (int off = 1; off < SCAN_BS; off <<= 1) {
        int s = in[t];
        if (t >= off) s += in[t - off];
        out[t] = s;
        __syncthreads();
        int* tmp = in; in = out; out = tmp;
    }
    if (t == SCAN_BS - 1) g_blocksums[blockIdx.x] = in[t];
    if (i < n) g_off[i] = in[t] - v;   // exclusive within block

    __threadfence();
    __shared__ int s_last;
    if (t == 0) s_last = (atomicAdd(&g_scan_done, 1) == nb - 1) ? 1 : 0;
    __syncthreads();
    if (s_last) {
        __shared__ int bs0[128];
        __shared__ int bs1[128];
        int bv = 0;
        if (t < 128) {
            bv = (t < nb) ? g_blocksums[t] : 0;
            bs0[t] = bv;
        }
        __syncthreads();
        int* bin = bs0;
        int* bout = bs1;
        #pragma unroll
        for (int off = 1; off < 128; off <<= 1) {
            if (t < 128) {
                int s = bin[t];
                if (t >= off) s += bin[t - off];
                bout[t] = s;
            }
            __syncthreads();
            int* tmp = bin; bin = bout; bout = tmp;
        }
        if (t < nb) g_blocksums[t] = bin[t] - bv;  // exclusive
    }
}

__global__ void scan_phase3(int n) {
    int i = blockIdx.x * SCAN_BS + threadIdx.x;
    if (i < n) {
        int s = g_off[i] + g_blocksums[blockIdx.x];
        g_off[i] = s;
        g_cursor[i] = s;
    }
}

__global__ void fill_buckets_kernel(const int* __restrict__ src,
                                    const int* __restrict__ dst, int E) {
    int e = blockIdx.x * blockDim.x + threadIdx.x;
    if (e < E) {
        int pos = atomicAdd(&g_cursor[dst[e]], 1);
        g_eidx[pos] = src[e];
    }
}

// ---------------------------------------------------------------------------
// Persistent fused kernel: each block loads weights into smem ONCE, then
// loops over 32-node tiles: (a) gather-aggregate h tile into smem from CSR
// (no atomics), (b) GEMM epilogue with packed f32x2 FMAs:
//   out[n][o] = sum_f h[n][f]*W_lin[o][f] + x[n][f]*W_self[o][f] + b[o]
// ---------------------------------------------------------------------------
__global__ void __launch_bounds__(256, 3)
fused_persistent_kernel(const float* __restrict__ x,
                        const float* __restrict__ W_lin,
                        const float* __restrict__ b_lin,
                        const float* __restrict__ W_self,
                        const float* __restrict__ b_self,
                        const float* __restrict__ bias,
                        float* __restrict__ out,
                        int N, int ntiles) {
    __shared__ float sWl[64 * 64];       // layout: [f4][o][4]
    __shared__ float sWs[64 * 64];
    __shared__ float4 sh4[32 * 16];      // h tile: 32 nodes x 64 floats (8KB)

    const float4* __restrict__ x4 = (const float4*)x;
    int tid = threadIdx.x;

    // Weights (transposed) — loaded once per block.
    #pragma unroll
    for (int i = tid; i < 64 * 64; i += 256) {
        int o = i >> 6;
        int f = i & 63;
        int dsti = (f >> 2) * 256 + o * 4 + (f & 3);
        sWl[dsti] = W_lin[i];
        sWs[dsti] = W_self[i];
    }

    int o = tid & 63;
    float b = b_lin[o] + b_self[o] + bias[o];

    // Gather-phase ids: 8 threads per node, each owns f4 chunks l and l+8.
    int nl = tid >> 3;          // local node 0..31
    int l  = tid & 7;

    // GEMM-phase ids: group g = tid>>6 (0..3), 8 nodes per thread.
    int g = tid >> 6;

    __syncthreads();   // weights ready

    for (int tile = blockIdx.x; tile < ntiles; tile += gridDim.x) {
        int tbase = tile * 32;

        // ---- Phase A: gather-aggregate ----
        {
            int node = tbase + nl;
            float4 aA0 = make_float4(0.f, 0.f, 0.f, 0.f);
            float4 aA1 = aA0, aB0 = aA0, aB1 = aA0;
            if (node < N) {
                int beg = g_off[node];
                int cnt = g_deg[node];
                int j = 0;
                for (; j + 2 <= cnt; j += 2) {
                    int s0 = __ldg(g_eidx + beg + j + 0);
                    int s1 = __ldg(g_eidx + beg + j + 1);
                    float4 vA0 = __ldg(x4 + (size_t)s0 * 16 + l);
                    float4 vB0 = __ldg(x4 + (size_t)s0 * 16 + l + 8);
                    float4 vA1 = __ldg(x4 + (size_t)s1 * 16 + l);
                    float4 vB1 = __ldg(x4 + (size_t)s1 * 16 + l + 8);
                    aA0.x += vA0.x; aA0.y += vA0.y; aA0.z += vA0.z; aA0.w += vA0.w;
                    aB0.x += vB0.x; aB0.y += vB0.y; aB0.z += vB0.z; aB0.w += vB0.w;
                    aA1.x += vA1.x; aA1.y += vA1.y; aA1.z += vA1.z; aA1.w += vA1.w;
                    aB1.x += vB1.x; aB1.y += vB1.y; aB1.z += vB1.z; aB1.w += vB1.w;
                }
                if (j < cnt) {
                    int s = __ldg(g_eidx + beg + j);
                    float4 vA = __ldg(x4 + (size_t)s * 16 + l);
                    float4 vB = __ldg(x4 + (size_t)s * 16 + l + 8);
                    aA0.x += vA.x; aA0.y += vA.y; aA0.z += vA.z; aA0.w += vA.w;
                    aB0.x += vB.x; aB0.y += vB.y; aB0.z += vB.z; aB0.w += vB.w;
                }
            }
            float4 rA, rB;
            rA.x = aA0.x + aA1.x; rA.y = aA0.y + aA1.y;
            rA.z = aA0.z + aA1.z; rA.w = aA0.w + aA1.w;
            rB.x = aB0.x + aB1.x; rB.y = aB0.y + aB1.y;
            rB.z = aB0.z + aB1.z; rB.w = aB0.w + aB1.w;
            sh4[nl * 16 + l] = rA;
            sh4[nl * 16 + l + 8] = rB;
        }
        __syncthreads();   // h tile ready

        // ---- Phase B: GEMM (8 nodes per thread) ----
        {
            int n0l = g * 8;
            int n0 = tbase + n0l;
            const float* __restrict__ hbase = (const float*)sh4 + n0l * 64;
            const float* __restrict__ xbase = x + (size_t)n0 * 64;

            if (n0 + 7 < N) {
                unsigned long long acc[8];
                unsigned long long binit = pack_f32x2(b, 0.f);
                #pragma unroll
                for (int k = 0; k < 8; k++) acc[k] = binit;

                #pragma unroll
                for (int f4 = 0; f4 < 16; f4++) {
                    ulonglong2 wl = *reinterpret_cast<const ulonglong2*>(
                                        &sWl[f4 * 256 + o * 4]);
                    ulonglong2 ws = *reinterpret_cast<const ulonglong2*>(
                                        &sWs[f4 * 256 + o * 4]);
                    #pragma unroll
                    for (int k = 0; k < 8; k++) {
                        ulonglong2 h = *reinterpret_cast<const ulonglong2*>(
                                           hbase + k * 64 + f4 * 4);
                        ulonglong2 xv = *reinterpret_cast<const ulonglong2*>(
                                            xbase + k * 64 + f4 * 4);
                        acc[k] = fma_f32x2(h.x, wl.x, acc[k]);
                        acc[k] = fma_f32x2(h.y, wl.y, acc[k]);
                        acc[k] = fma_f32x2(xv.x, ws.x, acc[k]);
                        acc[k] = fma_f32x2(xv.y, ws.y, acc[k]);
                    }
                }
                float* op = out + (size_t)n0 * 64 + o;
                #pragma unroll
                for (int k = 0; k < 8; k++) op[k * 64] = sum_f32x2(acc[k]);
            } else {
                for (int k = 0; k < 8; k++) {
                    int n = n0 + k;
                    if (n >= N) break;
                    float a = b;
                    for (int f = 0; f < 64; f++) {
                        a += hbase[k * 64 + f]
                               * sWl[(f >> 2) * 256 + o * 4 + (f & 3)]
                           + xbase[k * 64 + f]
                               * sWs[(f >> 2) * 256 + o * 4 + (f & 3)];
                    }
                    out[(size_t)n * 64 + o] = a;
                }
            }
        }
        __syncthreads();   // protect sh4 before next tile's gather
    }
}

// ---------------------------------------------------------------------------
// Launch. Input order: x, src, dst, W_lin, b_lin, W_self, b_self, bias
// ---------------------------------------------------------------------------
extern "C" void kernel_launch(void* const* d_in, const int* in_sizes, int n_in,
                              void* d_out, int out_size) {
    const float* x      = (const float*)d_in[0];
    const int*   src    = (const int*)d_in[1];
    const int*   dst    = (const int*)d_in[2];
    const float* W_lin  = (const float*)d_in[3];
    const float* b_lin  = (const float*)d_in[4];
    const float* W_self = (const float*)d_in[5];
    const float* b_self = (const float*)d_in[6];
    const float* bias   = (const float*)d_in[7];
    float* out = (float*)d_out;

    int N = in_sizes[0] / IN_F;   // 100000
    int E = in_sizes[1];          // 1280000
    int nb = (N + SCAN_BS - 1) / SCAN_BS;   // 98

    // CSR build (5 launches)
    zero_deg_kernel<<<(N + 255) / 256, 256>>>(N);
    count_deg_kernel<<<(E + 255) / 256, 256>>>(dst, E);
    scan_phase1<<<nb, SCAN_BS>>>(N, nb);
    scan_phase3<<<nb, SCAN_BS>>>(N);
    fill_buckets_kernel<<<(E + 255) / 256, 256>>>(src, dst, E);

    // Persistent fused gather + GEMM (6th launch -> profiled by ncu -s 5)
    int ntiles = (N + 31) / 32;
    int grid = 148 * 3;
    if (grid > ntiles) grid = ntiles;
    fused_persistent_kernel<<<grid, 256>>>(x, W_lin, b_lin, W_self, b_self,
                                           bias, out, N, ntiles);
}